// round 12
// baseline (speedup 1.0000x reference)
#include <cuda_runtime.h>
#include <cuda_fp16.h>
#include <math.h>
#include <stdint.h>

#define Bc   4
#define Gc   16906
#define Nc   16907
#define BNc  (Bc*Nc)          // 67628
#define Dc   256
#define Hc   8
#define DHc  32
#define Mc   110
#define Lc   6
#define FFc  1024
#define BHc  (Bc*Hc)          // 32
#define CH   40               // ctx reduction chunks
#define CR   423              // rows per chunk

#define XN_SCALE   0.42044820762685725f   // 32^-0.25
#define M_RSQRT    0.09534625892455922f   // 110^-0.5
#define FEPS       1e-4f

// ---------------- device scratch ----------------
__device__ __align__(128) float g_x[BNc*Dc];
__device__ __align__(128) __half g_qkvh[(size_t)3*BNc*Dc];
__device__ __align__(128) __half g_hh[BNc*Dc];
__device__ __align__(128) __half g_oh[BNc*Dc];
__device__ __align__(128) __half g_ffh[(size_t)BNc*FFc];
#define WSTRIDE 786432
__device__ __align__(128) __half g_wt[(size_t)Lc*WSTRIDE];
__device__ __align__(128) float g_kf[(size_t)BHc*Nc*Mc];
__device__ __align__(128) float g_diagk[(size_t)BHc*Nc];
__device__ __align__(128) float g_e[Bc*Gc];
__device__ float    g_rowsum[Bc];
__device__ unsigned g_umax;
__device__ unsigned g_ustab[Lc];
__device__ __align__(128) float g_ctx[BHc*Mc*DHc];
__device__ __align__(128) float g_ksum[BHc*Mc];
__device__ __align__(128) float g_ctxp[(size_t)CH*BHc*Mc*DHc];
__device__ __align__(128) float g_ksump[(size_t)CH*BHc*Mc];

__device__ __forceinline__ unsigned fflip(float f){
    unsigned u = __float_as_uint(f);
    return (u & 0x80000000u) ? ~u : (u | 0x80000000u);
}
__device__ __forceinline__ float funflip(unsigned u){
    unsigned b = (u & 0x80000000u) ? (u ^ 0x80000000u) : ~u;
    return __uint_as_float(b);
}
__device__ __forceinline__ float gelu_exact(float x){
    return 0.5f*x*(1.0f + erff(x*0.7071067811865476f));
}
__device__ __forceinline__ unsigned pkh2(float a, float b){
    unsigned ua = __half_as_ushort(__float2half(a));
    unsigned ub = __half_as_ushort(__float2half(b));
    return ua | (ub<<16);
}

__device__ __forceinline__ uint32_t smem_u32(const void* p) {
    uint32_t a;
    asm("{ .reg .u64 t; cvta.to.shared.u64 t, %1; cvt.u32.u64 %0, t; }" : "=r"(a) : "l"(p));
    return a;
}
__device__ __forceinline__ void cp_async16(uint32_t saddr, const void* gaddr, int srcsz){
    asm volatile("cp.async.cg.shared.global [%0], [%1], 16, %2;"
                 :: "r"(saddr), "l"(gaddr), "r"(srcsz) : "memory");
}
__device__ __forceinline__ void cp_commit(){ asm volatile("cp.async.commit_group;" ::: "memory"); }
__device__ __forceinline__ void cp_wait1(){ asm volatile("cp.async.wait_group 1;" ::: "memory"); }

__device__ __forceinline__ void mma_f16(float* d, const uint32_t* a, const uint32_t* b){
    asm volatile(
      "mma.sync.aligned.m16n8k16.row.col.f32.f16.f16.f32 "
      "{%0,%1,%2,%3}, {%4,%5,%6,%7}, {%8,%9}, {%0,%1,%2,%3};\n"
      : "+f"(d[0]), "+f"(d[1]), "+f"(d[2]), "+f"(d[3])
      : "r"(a[0]), "r"(a[1]), "r"(a[2]), "r"(a[3]), "r"(b[0]), "r"(b[1]));
}
__device__ __forceinline__ void ldsm4(uint32_t* r, uint32_t addr){
    asm volatile("ldmatrix.sync.aligned.m8n8.x4.shared.b16 {%0,%1,%2,%3}, [%4];"
                 : "=r"(r[0]), "=r"(r[1]), "=r"(r[2]), "=r"(r[3]) : "r"(addr));
}

// ---------------- preprocessing ----------------
__global__ void init_kernel(){
    g_umax = 0u;
    for(int l=0;l<Lc;l++) g_ustab[l] = 0u;
}

__global__ void rowsum_kernel(const float* __restrict__ expr){
    __shared__ float sred[256];
    int b = blockIdx.x;
    float s = 0.f;
    for(int i=threadIdx.x;i<Gc;i+=256) s += fabsf(expr[(size_t)b*Gc+i]);
    sred[threadIdx.x]=s; __syncthreads();
    for(int st=128;st;st>>=1){ if(threadIdx.x<st) sred[threadIdx.x]+=sred[threadIdx.x+st]; __syncthreads(); }
    if(threadIdx.x==0) g_rowsum[b]=sred[0];
}

__global__ void emax_kernel(const float* __restrict__ expr){
    __shared__ float sred[256];
    int i = blockIdx.x*256 + threadIdx.x;
    float e = 0.f;
    if(i < Bc*Gc){
        int b = i / Gc;
        float denom = fmaxf(g_rowsum[b], 1e-12f);
        e = log1pf(expr[i]/denom*1e4f);
        g_e[i] = e;
    }
    sred[threadIdx.x]=e; __syncthreads();
    for(int st=128;st;st>>=1){ if(threadIdx.x<st) sred[threadIdx.x]=fmaxf(sred[threadIdx.x],sred[threadIdx.x+st]); __syncthreads(); }
    if(threadIdx.x==0) atomicMax(&g_umax, fflip(sred[0]));
}

__global__ void embed_kernel(const float* __restrict__ temb, const float* __restrict__ cls){
    int row = blockIdx.x;
    int b = row / Nc, n = row % Nc;
    int d = threadIdx.x;
    float v;
    if(n==0){
        v = cls[d];
    } else {
        float e = g_e[b*Gc + n - 1];
        float maxe = funflip(g_umax);
        float step = maxe/7.0f;
        int t = (0.0f < e) ? 1 : 0;
        #pragma unroll
        for(int j=1;j<7;j++) t += ((float)j*step < e) ? 1 : 0;
        if(t>6) t=6;
        v = temb[t*Dc + d];
    }
    g_x[(size_t)row*Dc + d] = v;
}

// ---------------- weight transpose -> fp16 ----------------
__global__ void wconv_kernel(const float* __restrict__ W, __half* __restrict__ T, int K, int N){
    int idx = blockIdx.x*256 + threadIdx.x;
    if(idx >= K*N) return;
    int k = idx / N, n = idx % N;
    T[(size_t)n*K+k] = __float2half(W[idx]);
}

// ---------------- layernorm -> fp16 ----------------
__global__ void ln_kernel(const float* __restrict__ X, const float* __restrict__ g,
                          const float* __restrict__ bb, __half* __restrict__ Yh){
    int warp=threadIdx.x>>5, lane=threadIdx.x&31;
    int row = blockIdx.x*8 + warp;
    if(row>=BNc) return;
    const float4* xr=(const float4*)(X+(size_t)row*Dc);
    float4 v0=xr[lane], v1=xr[lane+32];
    float s = v0.x+v0.y+v0.z+v0.w+v1.x+v1.y+v1.z+v1.w;
    #pragma unroll
    for(int o=16;o;o>>=1) s += __shfl_xor_sync(0xffffffffu,s,o);
    float mu = s*(1.f/256.f);
    float d0=v0.x-mu,d1=v0.y-mu,d2=v0.z-mu,d3=v0.w-mu;
    float d4=v1.x-mu,d5=v1.y-mu,d6=v1.z-mu,d7=v1.w-mu;
    float sq = d0*d0+d1*d1+d2*d2+d3*d3+d4*d4+d5*d5+d6*d6+d7*d7;
    #pragma unroll
    for(int o=16;o;o>>=1) sq += __shfl_xor_sync(0xffffffffu,sq,o);
    float rstd = rsqrtf(sq*(1.f/256.f) + 1e-5f);
    float4 g0=((const float4*)g)[lane],  g1=((const float4*)g)[lane+32];
    float4 b0=((const float4*)bb)[lane], b1=((const float4*)bb)[lane+32];
    float y0=d0*rstd*g0.x+b0.x, y1=d1*rstd*g0.y+b0.y, y2=d2*rstd*g0.z+b0.z, y3=d3*rstd*g0.w+b0.w;
    float y4=d4*rstd*g1.x+b1.x, y5=d5*rstd*g1.y+b1.y, y6=d6*rstd*g1.z+b1.z, y7=d7*rstd*g1.w+b1.w;
    size_t base = (size_t)row*Dc;
    uint2 ph0; ph0.x = pkh2(y0,y1); ph0.y = pkh2(y2,y3);
    uint2 ph1; ph1.x = pkh2(y4,y5); ph1.y = pkh2(y6,y7);
    *(uint2*)(Yh + base + lane*4)       = ph0;
    *(uint2*)(Yh + base + 128 + lane*4) = ph1;
}

// ---------------- HMMA fp16 GEMM: 128x128 tile, 256 thr, K-chunk 64, 3-stage ring, 2 CTAs/SM ----------------
// C = A[Mr x Kd] @ B^T   (A,B fp16; B stored [N][K])
// EPI: 1 bias+residual->f32 ; 2 bias+gelu->fp16 ; 3 bias(routed)+QKV-plane routing ->fp16 planes
#define ASTR 72                   // fp16 elems per smem row (64 + 8 pad)
#define ARR_BYTES (128*ASTR*2)    // 18432
#define STG_BYTES (2*ARR_BYTES)   // 36864
#define NSTG 3
#define GEMM_SMEM (NSTG*STG_BYTES) // 110592

template<int EPI>
__global__ __launch_bounds__(256,2)
void hmma_gemm(const __half* __restrict__ A, const __half* __restrict__ B,
               const float* __restrict__ bias, const float* __restrict__ bias2, const float* __restrict__ bias3,
               const float* __restrict__ R,
               float* __restrict__ C, __half* __restrict__ Ch,
               int Mr, int Kd, int Nco)
{
    extern __shared__ char dynsm[];
    const int tid = threadIdx.x;
    const int wid = tid>>5, lane = tid&31;
    const int wm = wid>>2, wn = wid&3;      // 2 (m) x 4 (n), warp tile 64x32
    const int g = lane>>2, tg = lane&3;
    const int bx = blockIdx.x, by = blockIdx.y;
    const uint32_t sbase = smem_u32(dynsm);

    float acc[4][4][4];
    #pragma unroll
    for(int i=0;i<4;i++)
        #pragma unroll
        for(int j=0;j<4;j++)
            #pragma unroll
            for(int q=0;q<4;q++) acc[i][j][q]=0.f;

    const int nch = Kd >> 6;   // 64-wide K chunks

    // cp.async loader: 4 A rows + 4 B rows per thread (row = lrow + {0,32,64,96})
    const int lrow = tid>>3, lseg = tid&7;
    const uint32_t soff = (uint32_t)(lrow*(ASTR*2) + lseg*16);
    int arA[4], szA[4], bnr[4];
    #pragma unroll
    for(int gg=0; gg<4; gg++){
        int r = by*128 + lrow + gg*32;
        arA[gg] = (r < Mr) ? r : 0;
        szA[gg] = (r < Mr) ? 16 : 0;
        bnr[gg] = bx*128 + lrow + gg*32;
    }

    // ldmatrix per-lane offsets
    const int lr = (lane&7) + (lane&8);
    const uint32_t colb = (lane&16) ? 16u : 0u;
    const uint32_t aoff0 = (uint32_t)((wm*64 + lr)*(ASTR*2)) + colb;
    const uint32_t boff0 = (uint32_t)(ARR_BYTES + (wn*32 + lr)*(ASTR*2)) + colb;

    #define LOAD_STAGE(ch, st) do{ \
        int _k0 = (ch)<<6; \
        uint32_t _sb = sbase + (st)*STG_BYTES; \
        cp_async16(_sb + soff,                          A + (size_t)arA[0]*Kd + _k0 + lseg*8, szA[0]); \
        cp_async16(_sb + soff + 32*(ASTR*2),            A + (size_t)arA[1]*Kd + _k0 + lseg*8, szA[1]); \
        cp_async16(_sb + soff + 64*(ASTR*2),            A + (size_t)arA[2]*Kd + _k0 + lseg*8, szA[2]); \
        cp_async16(_sb + soff + 96*(ASTR*2),            A + (size_t)arA[3]*Kd + _k0 + lseg*8, szA[3]); \
        cp_async16(_sb + ARR_BYTES + soff,              B + (size_t)bnr[0]*Kd + _k0 + lseg*8, 16); \
        cp_async16(_sb + ARR_BYTES + soff + 32*(ASTR*2),B + (size_t)bnr[1]*Kd + _k0 + lseg*8, 16); \
        cp_async16(_sb + ARR_BYTES + soff + 64*(ASTR*2),B + (size_t)bnr[2]*Kd + _k0 + lseg*8, 16); \
        cp_async16(_sb + ARR_BYTES + soff + 96*(ASTR*2),B + (size_t)bnr[3]*Kd + _k0 + lseg*8, 16); \
        cp_commit(); \
    } while(0)

    LOAD_STAGE(0, 0);
    if(nch>1) LOAD_STAGE(1, 1); else cp_commit();

    int st = 0;
    for(int ch=0; ch<nch; ch++){
        cp_wait1();
        __syncthreads();
        const uint32_t sb = sbase + st*STG_BYTES;
        #pragma unroll
        for(int ks=0; ks<4; ks++){
            const uint32_t kbyte = ks*32;
            uint32_t b2[2][4];
            ldsm4(b2[0], sb + boff0 + kbyte);
            ldsm4(b2[1], sb + boff0 + (uint32_t)(16*(ASTR*2)) + kbyte);
            #pragma unroll
            for(int mt=0; mt<4; mt++){
                uint32_t ah[4];
                ldsm4(ah, sb + aoff0 + (uint32_t)(mt*16*(ASTR*2)) + kbyte);
                #pragma unroll
                for(int nt=0; nt<4; nt++){
                    const int n2 = nt>>1, od = nt&1;
                    uint32_t bb[2] = { b2[n2][od], b2[n2][od+2] };
                    mma_f16(acc[mt][nt], ah, bb);
                }
            }
        }
        // prefetch into the stage freed two iterations ago
        int nx = ch + NSTG - 1;
        int nst = st + 2; if(nst >= NSTG) nst -= NSTG;
        if(nx < nch) LOAD_STAGE(nx, nst); else cp_commit();
        st++; if(st == NSTG) st = 0;
    }

    // epilogue (direct per-thread stores)
    #pragma unroll
    for(int mt=0; mt<4; mt++){
        #pragma unroll
        for(int nt=0; nt<4; nt++){
            int c = bx*128 + wn*32 + nt*8 + tg*2;
            float bb0, bb1;
            if(EPI==3){
                const float* bp = (c<256) ? bias : ((c<512) ? bias2 : bias3);
                int cc = c & 255;
                bb0 = bp[cc]; bb1 = bp[cc+1];
            } else {
                bb0 = bias[c]; bb1 = bias[c+1];
            }
            #pragma unroll
            for(int hf=0; hf<2; hf++){
                int r = by*128 + wm*64 + mt*16 + g + hf*8;
                if(r >= Mr) continue;
                float v0 = acc[mt][nt][hf*2+0] + bb0;
                float v1 = acc[mt][nt][hf*2+1] + bb1;
                if(EPI==3){
                    int plane = c>>8, cc = c&255;
                    *(uint32_t*)(Ch + (size_t)plane*BNc*Dc + (size_t)r*Dc + cc) = pkh2(v0, v1);
                    continue;
                }
                size_t off = (size_t)r*Nco + c;
                if(EPI==1){
                    float2 rv = *(const float2*)(R + off);
                    v0 += rv.x; v1 += rv.y;
                    *(float2*)(C + off) = make_float2(v0, v1);
                }
                if(EPI==2){
                    v0 = gelu_exact(v0); v1 = gelu_exact(v1);
                    *(uint32_t*)(Ch + off) = pkh2(v0, v1);
                }
            }
        }
    }
}

// ---------------- FAVOR+ K features pass 1: raw dd + diag + global max ----------------
__global__ __launch_bounds__(256) void featk1_kernel(const __half* __restrict__ K, const float* __restrict__ proj, int l){
    int bh = blockIdx.y; int b = bh>>3, h = bh&7;
    int n0 = blockIdx.x*32;
    __shared__ float sprojT[32][112];
    __shared__ float sxn[32][32];
    __shared__ float sred[256];
    int tid = threadIdx.x;
    for(int idx=tid; idx<Mc*DHc; idx+=256){ int m=idx>>5, d=idx&31; sprojT[d][m]=proj[idx]; }
    {
        int r = tid>>3, q4 = tid&7; int n = n0+r;
        const __half* kp = K + (size_t)(b*Nc+n)*Dc + h*DHc + q4*4;
        if(n<Nc){
            __half2 p0 = *(const __half2*)kp;
            __half2 p1 = *(const __half2*)(kp+2);
            sxn[r][q4*4+0]=__half2float(p0.x)*XN_SCALE; sxn[r][q4*4+1]=__half2float(p0.y)*XN_SCALE;
            sxn[r][q4*4+2]=__half2float(p1.x)*XN_SCALE; sxn[r][q4*4+3]=__half2float(p1.y)*XN_SCALE;
        } else {
            sxn[r][q4*4+0]=0.f; sxn[r][q4*4+1]=0.f; sxn[r][q4*4+2]=0.f; sxn[r][q4*4+3]=0.f;
        }
    }
    __syncthreads();
    float lmax = -3.4e38f;
    for(int idx=tid; idx<32*Mc; idx+=256){
        int r=idx/Mc, m=idx%Mc; int n=n0+r;
        float acc=0.f;
        #pragma unroll
        for(int d=0;d<32;d++) acc += sxn[r][d]*sprojT[d][m];
        if(n<Nc){ g_kf[((size_t)bh*Nc+n)*Mc+m]=acc; lmax=fmaxf(lmax,acc); }
    }
    int warp=tid>>5, lane=tid&31;
    for(int r=warp;r<32;r+=8){
        float xv=sxn[r][lane]; float dg=xv*xv;
        #pragma unroll
        for(int o=16;o;o>>=1) dg+=__shfl_xor_sync(0xffffffffu,dg,o);
        int n=n0+r;
        if(lane==0 && n<Nc) g_diagk[(size_t)bh*Nc+n]=0.5f*dg;
    }
    sred[tid]=lmax; __syncthreads();
    for(int st=128;st;st>>=1){ if(tid<st) sred[tid]=fmaxf(sred[tid],sred[tid+st]); __syncthreads(); }
    if(tid==0) atomicMax(&g_ustab[l], fflip(sred[0]));
}

// ---------------- kf(raw)+exp -> ctx/ksum (chunked, deterministic) ----------------
__global__ __launch_bounds__(256) void ctx_partial_kernel(const __half* __restrict__ V, int l){
    int ch=blockIdx.x, bh=blockIdx.y; int b=bh>>3, h=bh&7;
    int nstart=ch*CR;
    int nend = nstart+CR < Nc ? nstart+CR : Nc;
    float stab = funflip(g_ustab[l]);
    __shared__ float skf[4][112];
    __shared__ float sv[4][32];
    int tid=threadIdx.x;
    int txd=tid&7, ty=tid>>3;
    float acc[4][4]; float ks[4];
    #pragma unroll
    for(int k=0;k<4;k++){ ks[k]=0.f;
        #pragma unroll
        for(int j=0;j<4;j++) acc[k][j]=0.f; }
    for(int n=nstart;n<nend;n+=4){
        __syncthreads();
        for(int idx=tid;idx<4*Mc;idx+=256){
            int nn=idx/Mc, m=idx%Mc; int gn=n+nn;
            float kv = 0.f;
            if(gn<nend){
                float raw = g_kf[((size_t)bh*Nc+gn)*Mc+m];
                float sub = g_diagk[(size_t)bh*Nc+gn] + stab;
                kv = M_RSQRT*(__expf(raw - sub) + FEPS);
            }
            skf[nn][m] = kv;
        }
        if(tid<128){
            int nn=tid>>5, d=tid&31; int gn=n+nn;
            sv[nn][d] = (gn<nend)? __half2float(V[((size_t)(b*Nc+gn))*Dc + h*DHc + d]) : 0.f;
        }
        __syncthreads();
        #pragma unroll
        for(int nn=0;nn<4;nn++){
            float4 vv = *(const float4*)&sv[nn][txd*4];
            #pragma unroll
            for(int k=0;k<4;k++){
                int m = ty + 32*k;
                if(m<Mc){
                    float kv = skf[nn][m];
                    acc[k][0]+=kv*vv.x; acc[k][1]+=kv*vv.y;
                    acc[k][2]+=kv*vv.z; acc[k][3]+=kv*vv.w;
                    if(txd==0) ks[k]+=kv;
                }
            }
        }
    }
    #pragma unroll
    for(int k=0;k<4;k++){
        int m = ty + 32*k;
        if(m<Mc){
            float* dst = g_ctxp + ((((size_t)ch*BHc+bh)*Mc+m)*DHc) + txd*4;
            dst[0]=acc[k][0]; dst[1]=acc[k][1]; dst[2]=acc[k][2]; dst[3]=acc[k][3];
            if(txd==0) g_ksump[((size_t)ch*BHc+bh)*Mc+m]=ks[k];
        }
    }
}

__global__ void ctx_reduce_kernel(){
    int bh = blockIdx.x;
    for(int idx=threadIdx.x; idx<Mc*DHc; idx+=256){
        float s=0.f;
        for(int ch=0;ch<CH;ch++) s += g_ctxp[((size_t)ch*BHc+bh)*Mc*DHc + idx];
        g_ctx[(size_t)bh*Mc*DHc + idx]=s;
    }
    for(int idx=threadIdx.x; idx<Mc; idx+=256){
        float s=0.f;
        for(int ch=0;ch<CH;ch++) s += g_ksump[((size_t)ch*BHc+bh)*Mc + idx];
        g_ksum[bh*Mc+idx]=s;
    }
}

// ---------------- fused: qf features + o = (qf @ ctx) / (qf . ksum) -> fp16 ----------------
#define AT_PROJ 0
#define AT_XN   3584
#define AT_QF   5696
#define AT_CTX  12928
#define AT_KS   16448
#define AT_DEN  16560
#define ATT_SMEM ((16560+64)*4)

__global__ __launch_bounds__(128) void attn_out_fused(const __half* __restrict__ Q, const float* __restrict__ proj){
    extern __shared__ float sm[];
    float* sprojT = sm + AT_PROJ;   // [32][112]
    float* sxn    = sm + AT_XN;     // [64][33]
    float* sqf    = sm + AT_QF;     // [64][113]
    float* sctx   = sm + AT_CTX;    // [110*32]
    float* sks    = sm + AT_KS;     // [112]
    float* sden   = sm + AT_DEN;    // [64]
    int bh = blockIdx.y; int b = bh>>3, h = bh&7;
    int n0 = blockIdx.x*64;
    int tid = threadIdx.x;

    for(int idx=tid; idx<Mc*DHc; idx+=128){ int m=idx>>5, d=idx&31; sprojT[d*112+m]=proj[idx]; }
    if(tid<64){ int d=tid>>1, m=110+(tid&1); sprojT[d*112+m]=0.f; }
    for(int idx=tid; idx<64*32; idx+=128){
        int r=idx>>5, d=idx&31; int n=n0+r;
        sxn[r*33+d] = (n<Nc)? __half2float(Q[((size_t)(b*Nc+n))*Dc + h*DHc + d])*XN_SCALE : 0.f;
    }
    for(int idx=tid; idx<Mc*DHc; idx+=128) sctx[idx]=g_ctx[(size_t)bh*Mc*DHc+idx];
    for(int idx=tid; idx<Mc; idx+=128) sks[idx]=g_ksum[bh*Mc+idx];
    __syncthreads();

    {
        int rg = tid>>4, ml = tid&15;
        for(int rb=0; rb<64; rb+=8){
            int r = rb + rg;
            float a[7];
            #pragma unroll
            for(int j=0;j<7;j++) a[j]=0.f;
            #pragma unroll
            for(int d=0; d<32; d++){
                float xv = sxn[r*33+d];
                #pragma unroll
                for(int j=0;j<7;j++) a[j] += xv * sprojT[d*112 + ml + j*16];
            }
            #pragma unroll
            for(int j=0;j<7;j++){ int m = ml + j*16; if(m<Mc) sqf[r*113+m]=a[j]; }
        }
    }
    __syncthreads();

    int warp=tid>>5, lane=tid&31;
    for(int r=warp; r<64; r+=4){
        float mx=-3.4e38f;
        for(int m=lane;m<Mc;m+=32) mx=fmaxf(mx, sqf[r*113+m]);
        #pragma unroll
        for(int o=16;o;o>>=1) mx=fmaxf(mx,__shfl_xor_sync(0xffffffffu,mx,o));
        float xv=sxn[r*33+lane]; float dg=xv*xv;
        #pragma unroll
        for(int o=16;o;o>>=1) dg+=__shfl_xor_sync(0xffffffffu,dg,o);
        float sub = 0.5f*dg + mx;
        for(int m=lane;m<Mc;m+=32)
            sqf[r*113+m] = M_RSQRT*(__expf(sqf[r*113+m]-sub) + FEPS);
    }
    __syncthreads();

    for(int r=warp; r<64; r+=4){
        float dp=0.f;
        for(int m=lane;m<Mc;m+=32) dp += sqf[r*113+m]*sks[m];
        #pragma unroll
        for(int o=16;o;o>>=1) dp += __shfl_xor_sync(0xffffffffu,dp,o);
        if(lane==0) sden[r]=dp;
    }
    __syncthreads();

    int tx = tid&7, ty = tid>>3;
    float acc[4][4];
    #pragma unroll
    for(int i=0;i<4;i++)
        #pragma unroll
        for(int j=0;j<4;j++) acc[i][j]=0.f;
    for(int m=0;m<Mc;m++){
        float4 cv = *(const float4*)&sctx[m*DHc + tx*4];
        #pragma unroll
        for(int i=0;i<4;i++){
            float qv = sqf[(ty*4+i)*113+m];
            acc[i][0]+=qv*cv.x; acc[i][1]+=qv*cv.y; acc[i][2]+=qv*cv.z; acc[i][3]+=qv*cv.w;
        }
    }
    #pragma unroll
    for(int i=0;i<4;i++){
        int r = ty*4+i; int n = n0+r;
        if(n<Nc){
            float inv = 1.f/sden[r];
            float v0=acc[i][0]*inv, v1=acc[i][1]*inv, v2=acc[i][2]*inv, v3=acc[i][3]*inv;
            size_t off = ((size_t)(b*Nc+n))*Dc + h*DHc + tx*4;
            uint2 ph; ph.x = pkh2(v0,v1); ph.y = pkh2(v2,v3);
            *(uint2*)(g_oh + off) = ph;
        }
    }
}

// ---------------- final projection ----------------
__global__ void final_kernel(const float* __restrict__ pw, const float* __restrict__ pb, float* __restrict__ out){
    int j = threadIdx.x;
    float a0=0,a1=0,a2=0,a3=0;
    for(int d=0;d<Dc;d++){
        float w = pw[d*Dc+j];
        a0 += g_x[(size_t)(0*Nc)*Dc + d]*w;
        a1 += g_x[(size_t)(1*Nc)*Dc + d]*w;
        a2 += g_x[(size_t)(2*Nc)*Dc + d]*w;
        a3 += g_x[(size_t)(3*Nc)*Dc + d]*w;
    }
    float bj = pb[j];
    out[0*Dc+j]=a0+bj; out[1*Dc+j]=a1+bj; out[2*Dc+j]=a2+bj; out[3*Dc+j]=a3+bj;
}

// ---------------- launch ----------------
extern "C" void kernel_launch(void* const* d_in, const int* in_sizes, int n_in,
                              void* d_out, int out_size){
    const float* expr      = (const float*)d_in[0];
    const float* token_emb = (const float*)d_in[1];
    const float* cls_token = (const float*)d_in[2];
    const float* ln1_g     = (const float*)d_in[3];
    const float* ln1_b     = (const float*)d_in[4];
    const float* wq        = (const float*)d_in[5];
    const float* bq        = (const float*)d_in[6];
    const float* wk        = (const float*)d_in[7];
    const float* bk        = (const float*)d_in[8];
    const float* wv        = (const float*)d_in[9];
    const float* bv        = (const float*)d_in[10];
    const float* wo        = (const float*)d_in[11];
    const float* bo        = (const float*)d_in[12];
    const float* ln2_g     = (const float*)d_in[13];
    const float* ln2_b     = (const float*)d_in[14];
    const float* w1        = (const float*)d_in[15];
    const float* b1        = (const float*)d_in[16];
    const float* w2        = (const float*)d_in[17];
    const float* b2        = (const float*)d_in[18];
    const float* proj_w    = (const float*)d_in[19];
    const float* proj_b    = (const float*)d_in[20];
    const float* projs     = (const float*)d_in[21];
    float* out = (float*)d_out;

    float *px;
    __half *pqkvh, *phh, *poh, *pffh, *pw;
    cudaGetSymbolAddress((void**)&px,    g_x);
    cudaGetSymbolAddress((void**)&pqkvh, g_qkvh);
    cudaGetSymbolAddress((void**)&phh,   g_hh);
    cudaGetSymbolAddress((void**)&poh,   g_oh);
    cudaGetSymbolAddress((void**)&pffh,  g_ffh);
    cudaGetSymbolAddress((void**)&pw,    g_wt);
    __half* pq = pqkvh;
    __half* pk = pqkvh + (size_t)BNc*Dc;
    __half* pv = pqkvh + (size_t)2*BNc*Dc;

    cudaFuncSetAttribute(hmma_gemm<1>, cudaFuncAttributeMaxDynamicSharedMemorySize, GEMM_SMEM);
    cudaFuncSetAttribute(hmma_gemm<2>, cudaFuncAttributeMaxDynamicSharedMemorySize, GEMM_SMEM);
    cudaFuncSetAttribute(hmma_gemm<3>, cudaFuncAttributeMaxDynamicSharedMemorySize, GEMM_SMEM);
    cudaFuncSetAttribute(attn_out_fused, cudaFuncAttributeMaxDynamicSharedMemorySize, ATT_SMEM);

    init_kernel<<<1,1>>>();
    rowsum_kernel<<<Bc,256>>>(expr);
    emax_kernel<<<(Bc*Gc+255)/256,256>>>(expr);
    embed_kernel<<<BNc,256>>>(token_emb, cls_token);

    // weight conversion: transpose -> fp16 (QKV rows 0-767 fused layout)
    for(int l=0;l<Lc;l++){
        size_t wb = (size_t)l*WSTRIDE;
        wconv_kernel<<<(Dc*Dc+255)/256,256>>>(wq + (size_t)l*Dc*Dc, pw+wb,        Dc, Dc);
        wconv_kernel<<<(Dc*Dc+255)/256,256>>>(wk + (size_t)l*Dc*Dc, pw+wb+65536,  Dc, Dc);
        wconv_kernel<<<(Dc*Dc+255)/256,256>>>(wv + (size_t)l*Dc*Dc, pw+wb+131072, Dc, Dc);
        wconv_kernel<<<(Dc*Dc+255)/256,256>>>(wo + (size_t)l*Dc*Dc, pw+wb+196608, Dc, Dc);
        wconv_kernel<<<(Dc*FFc+255)/256,256>>>(w1 + (size_t)l*Dc*FFc, pw+wb+262144, Dc, FFc);
        wconv_kernel<<<(Dc*FFc+255)/256,256>>>(w2 + (size_t)l*FFc*Dc, pw+wb+524288, FFc, Dc);
    }

    const int GY = (BNc+127)/128;          // 529
    dim3 gQKV(6, GY);                      // N=768
    dim3 gD(Dc/128, GY);                   // (2, 529)
    dim3 gFF(FFc/128, GY);                 // (8, 529)
    dim3 gfeat((Nc+31)/32, BHc);
    dim3 gctx(CH, BHc);
    dim3 gattn((Nc+63)/64, BHc);
    int lnb = (BNc+7)/8;

    for(int l=0;l<Lc;l++){
        size_t wb = (size_t)l*WSTRIDE;
        const __half *wqkv=pw+wb;
        const __half *wo_t=pw+wb+196608;
        const __half *w1_t=pw+wb+262144;
        const __half *w2_t=pw+wb+524288;
        const float* pr_l = projs + (size_t)l*Mc*DHc;

        ln_kernel<<<lnb,256>>>(px, ln1_g + l*Dc, ln1_b + l*Dc, phh);
        hmma_gemm<3><<<gQKV,256,GEMM_SMEM>>>(phh, wqkv,
                                             bq + l*Dc, bk + l*Dc, bv + l*Dc,
                                             nullptr, nullptr, pqkvh, BNc, Dc, 768);
        featk1_kernel<<<gfeat,256>>>(pk, pr_l, l);
        ctx_partial_kernel<<<gctx,256>>>(pv, l);
        ctx_reduce_kernel<<<BHc,256>>>();
        attn_out_fused<<<gattn,128,ATT_SMEM>>>(pq, pr_l);
        hmma_gemm<1><<<gD,256,GEMM_SMEM>>>(poh, wo_t,
                                           bo + l*Dc, nullptr, nullptr,
                                           px, px, nullptr, BNc, Dc, Dc);
        ln_kernel<<<lnb,256>>>(px, ln2_g + l*Dc, ln2_b + l*Dc, phh);
        hmma_gemm<2><<<gFF,256,GEMM_SMEM>>>(phh, w1_t,
                                            b1 + l*FFc, nullptr, nullptr,
                                            nullptr, nullptr, pffh, BNc, Dc, FFc);
        hmma_gemm<1><<<gD,256,GEMM_SMEM>>>(pffh, w2_t,
                                           b2 + l*Dc, nullptr, nullptr,
                                           px, px, nullptr, BNc, FFc, Dc);
    }
    final_kernel<<<1,256>>>(proj_w, proj_b, out);
}

// round 13
// speedup vs baseline: 1.0028x; 1.0028x over previous
#include <cuda_runtime.h>
#include <cuda_fp16.h>
#include <math.h>
#include <stdint.h>

#define Bc   4
#define Gc   16906
#define Nc   16907
#define BNc  (Bc*Nc)          // 67628
#define Dc   256
#define Hc   8
#define DHc  32
#define Mc   110
#define Lc   6
#define FFc  1024
#define BHc  (Bc*Hc)          // 32
#define CH   40               // ctx reduction chunks
#define CR   423              // rows per chunk

#define XN_SCALE   0.42044820762685725f   // 32^-0.25
#define M_RSQRT    0.09534625892455922f   // 110^-0.5
#define FEPS       1e-4f

// ---------------- device scratch ----------------
__device__ __align__(128) float g_x[BNc*Dc];
__device__ __align__(128) __half g_qkvh[(size_t)3*BNc*Dc];
__device__ __align__(128) __half g_hh[BNc*Dc];
__device__ __align__(128) __half g_oh[BNc*Dc];
__device__ __align__(128) __half g_ffh[(size_t)BNc*FFc];
#define WSTRIDE 786432
__device__ __align__(128) __half g_wt[(size_t)Lc*WSTRIDE];
__device__ __align__(128) float g_e[Bc*Gc];
__device__ float    g_rowsum[Bc];
__device__ unsigned g_umax;
__device__ unsigned g_ustab[Lc];
__device__ __align__(128) float g_ctx[BHc*Mc*DHc];
__device__ __align__(128) float g_ksum[BHc*Mc];
__device__ __align__(128) float g_ctxp[(size_t)CH*BHc*Mc*DHc];
__device__ __align__(128) float g_ksump[(size_t)CH*BHc*Mc];

__device__ __forceinline__ unsigned fflip(float f){
    unsigned u = __float_as_uint(f);
    return (u & 0x80000000u) ? ~u : (u | 0x80000000u);
}
__device__ __forceinline__ float funflip(unsigned u){
    unsigned b = (u & 0x80000000u) ? (u ^ 0x80000000u) : ~u;
    return __uint_as_float(b);
}
__device__ __forceinline__ float gelu_exact(float x){
    return 0.5f*x*(1.0f + erff(x*0.7071067811865476f));
}
__device__ __forceinline__ unsigned pkh2(float a, float b){
    unsigned ua = __half_as_ushort(__float2half(a));
    unsigned ub = __half_as_ushort(__float2half(b));
    return ua | (ub<<16);
}

__device__ __forceinline__ uint32_t smem_u32(const void* p) {
    uint32_t a;
    asm("{ .reg .u64 t; cvta.to.shared.u64 t, %1; cvt.u32.u64 %0, t; }" : "=r"(a) : "l"(p));
    return a;
}
__device__ __forceinline__ void cp_async16(uint32_t saddr, const void* gaddr, int srcsz){
    asm volatile("cp.async.cg.shared.global [%0], [%1], 16, %2;"
                 :: "r"(saddr), "l"(gaddr), "r"(srcsz) : "memory");
}
__device__ __forceinline__ void cp_commit(){ asm volatile("cp.async.commit_group;" ::: "memory"); }
__device__ __forceinline__ void cp_wait2(){ asm volatile("cp.async.wait_group 2;" ::: "memory"); }
__device__ __forceinline__ void cp_wait0(){ asm volatile("cp.async.wait_group 0;" ::: "memory"); }

__device__ __forceinline__ void mma_f16(float* d, const uint32_t* a, const uint32_t* b){
    asm volatile(
      "mma.sync.aligned.m16n8k16.row.col.f32.f16.f16.f32 "
      "{%0,%1,%2,%3}, {%4,%5,%6,%7}, {%8,%9}, {%0,%1,%2,%3};\n"
      : "+f"(d[0]), "+f"(d[1]), "+f"(d[2]), "+f"(d[3])
      : "r"(a[0]), "r"(a[1]), "r"(a[2]), "r"(a[3]), "r"(b[0]), "r"(b[1]));
}
__device__ __forceinline__ void ldsm4(uint32_t* r, uint32_t addr){
    asm volatile("ldmatrix.sync.aligned.m8n8.x4.shared.b16 {%0,%1,%2,%3}, [%4];"
                 : "=r"(r[0]), "=r"(r[1]), "=r"(r[2]), "=r"(r[3]) : "r"(addr));
}

// ---------------- preprocessing ----------------
__global__ void init_kernel(){
    g_umax = 0u;
    for(int l=0;l<Lc;l++) g_ustab[l] = 0u;
}

__global__ void rowsum_kernel(const float* __restrict__ expr){
    __shared__ float sred[256];
    int b = blockIdx.x;
    float s = 0.f;
    for(int i=threadIdx.x;i<Gc;i+=256) s += fabsf(expr[(size_t)b*Gc+i]);
    sred[threadIdx.x]=s; __syncthreads();
    for(int st=128;st;st>>=1){ if(threadIdx.x<st) sred[threadIdx.x]+=sred[threadIdx.x+st]; __syncthreads(); }
    if(threadIdx.x==0) g_rowsum[b]=sred[0];
}

__global__ void emax_kernel(const float* __restrict__ expr){
    __shared__ float sred[256];
    int i = blockIdx.x*256 + threadIdx.x;
    float e = 0.f;
    if(i < Bc*Gc){
        int b = i / Gc;
        float denom = fmaxf(g_rowsum[b], 1e-12f);
        e = log1pf(expr[i]/denom*1e4f);
        g_e[i] = e;
    }
    sred[threadIdx.x]=e; __syncthreads();
    for(int st=128;st;st>>=1){ if(threadIdx.x<st) sred[threadIdx.x]=fmaxf(sred[threadIdx.x],sred[threadIdx.x+st]); __syncthreads(); }
    if(threadIdx.x==0) atomicMax(&g_umax, fflip(sred[0]));
}

__global__ void embed_kernel(const float* __restrict__ temb, const float* __restrict__ cls){
    int row = blockIdx.x;
    int b = row / Nc, n = row % Nc;
    int d = threadIdx.x;
    float v;
    if(n==0){
        v = cls[d];
    } else {
        float e = g_e[b*Gc + n - 1];
        float maxe = funflip(g_umax);
        float step = maxe/7.0f;
        int t = (0.0f < e) ? 1 : 0;
        #pragma unroll
        for(int j=1;j<7;j++) t += ((float)j*step < e) ? 1 : 0;
        if(t>6) t=6;
        v = temb[t*Dc + d];
    }
    g_x[(size_t)row*Dc + d] = v;
}

// ---------------- weight transpose -> fp16 ----------------
__global__ void wconv_kernel(const float* __restrict__ W, __half* __restrict__ T, int K, int N){
    int idx = blockIdx.x*256 + threadIdx.x;
    if(idx >= K*N) return;
    int k = idx / N, n = idx % N;
    T[(size_t)n*K+k] = __float2half(W[idx]);
}

// ---------------- layernorm -> fp16 ----------------
__global__ void ln_kernel(const float* __restrict__ X, const float* __restrict__ g,
                          const float* __restrict__ bb, __half* __restrict__ Yh){
    int warp=threadIdx.x>>5, lane=threadIdx.x&31;
    int row = blockIdx.x*8 + warp;
    if(row>=BNc) return;
    const float4* xr=(const float4*)(X+(size_t)row*Dc);
    float4 v0=xr[lane], v1=xr[lane+32];
    float s = v0.x+v0.y+v0.z+v0.w+v1.x+v1.y+v1.z+v1.w;
    #pragma unroll
    for(int o=16;o;o>>=1) s += __shfl_xor_sync(0xffffffffu,s,o);
    float mu = s*(1.f/256.f);
    float d0=v0.x-mu,d1=v0.y-mu,d2=v0.z-mu,d3=v0.w-mu;
    float d4=v1.x-mu,d5=v1.y-mu,d6=v1.z-mu,d7=v1.w-mu;
    float sq = d0*d0+d1*d1+d2*d2+d3*d3+d4*d4+d5*d5+d6*d6+d7*d7;
    #pragma unroll
    for(int o=16;o;o>>=1) sq += __shfl_xor_sync(0xffffffffu,sq,o);
    float rstd = rsqrtf(sq*(1.f/256.f) + 1e-5f);
    float4 g0=((const float4*)g)[lane],  g1=((const float4*)g)[lane+32];
    float4 b0=((const float4*)bb)[lane], b1=((const float4*)bb)[lane+32];
    float y0=d0*rstd*g0.x+b0.x, y1=d1*rstd*g0.y+b0.y, y2=d2*rstd*g0.z+b0.z, y3=d3*rstd*g0.w+b0.w;
    float y4=d4*rstd*g1.x+b1.x, y5=d5*rstd*g1.y+b1.y, y6=d6*rstd*g1.z+b1.z, y7=d7*rstd*g1.w+b1.w;
    size_t base = (size_t)row*Dc;
    uint2 ph0; ph0.x = pkh2(y0,y1); ph0.y = pkh2(y2,y3);
    uint2 ph1; ph1.x = pkh2(y4,y5); ph1.y = pkh2(y6,y7);
    *(uint2*)(Yh + base + lane*4)       = ph0;
    *(uint2*)(Yh + base + 128 + lane*4) = ph1;
}

// ---------------- HMMA fp16 GEMM (R11 config: 128x128 tile, 256 thr, 4-stage ring, 2 CTAs/SM) ----------------
// C = A[Mr x Kd] @ B^T   (A,B fp16; B stored [N][K])
// EPI: 1 bias+residual->f32 ; 2 bias+gelu->fp16 ; 3 bias(routed)+QKV-plane routing ->fp16 planes
#define ASTR 40                   // fp16 elems per smem row (32 + 8 pad)
#define ARR_BYTES (128*ASTR*2)    // 10240
#define STG_BYTES (2*ARR_BYTES)   // 20480
#define NSTG 4
#define GEMM_SMEM (NSTG*STG_BYTES) // 81920

template<int EPI>
__global__ __launch_bounds__(256,2)
void hmma_gemm(const __half* __restrict__ A, const __half* __restrict__ B,
               const float* __restrict__ bias, const float* __restrict__ bias2, const float* __restrict__ bias3,
               const float* __restrict__ R,
               float* __restrict__ C, __half* __restrict__ Ch,
               int Mr, int Kd, int Nco)
{
    extern __shared__ char dynsm[];
    const int tid = threadIdx.x;
    const int wid = tid>>5, lane = tid&31;
    const int wm = wid>>2, wn = wid&3;      // 2 (m) x 4 (n), warp tile 64x32
    const int g = lane>>2, tg = lane&3;
    const int bx = blockIdx.x, by = blockIdx.y;
    const uint32_t sbase = smem_u32(dynsm);

    float acc[4][4][4];
    #pragma unroll
    for(int i=0;i<4;i++)
        #pragma unroll
        for(int j=0;j<4;j++)
            #pragma unroll
            for(int q=0;q<4;q++) acc[i][j][q]=0.f;

    const int nch = Kd >> 5;

    // cp.async loader indices (per thread: 2 rows of 16B per array)
    const int p0row = tid>>2,            p0q = tid&3;
    const int p1row = (tid+256)>>2,      p1q = tid&3;
    const int ar0 = by*128 + p0row, ar1 = by*128 + p1row;
    const int ar0c = ar0 < Mr ? ar0 : 0;  const int a0sz = ar0 < Mr ? 16 : 0;
    const int ar1c = ar1 < Mr ? ar1 : 0;  const int a1sz = ar1 < Mr ? 16 : 0;
    const int bn0 = bx*128 + p0row, bn1 = bx*128 + p1row;
    const uint32_t so0 = (uint32_t)(p0row*80 + p0q*16);
    const uint32_t so1 = (uint32_t)(p1row*80 + p1q*16);

    // ldmatrix per-lane offsets
    const int lr = (lane&7) + (lane&8);
    const uint32_t colb = (lane&16) ? 16u : 0u;
    const uint32_t aoff0 = (uint32_t)((wm*64 + lr)*ASTR*2) + colb;
    const uint32_t boff0 = (uint32_t)(ARR_BYTES + (wn*32 + lr)*ASTR*2) + colb;

    #define LOAD_STAGE(ch, st) do{ \
        int _k0 = (ch)<<5; \
        uint32_t _sb = sbase + (st)*STG_BYTES; \
        cp_async16(_sb + so0,             A + (size_t)ar0c*Kd + _k0 + p0q*8, a0sz); \
        cp_async16(_sb + so1,             A + (size_t)ar1c*Kd + _k0 + p1q*8, a1sz); \
        cp_async16(_sb + ARR_BYTES + so0, B + (size_t)bn0*Kd + _k0 + p0q*8, 16); \
        cp_async16(_sb + ARR_BYTES + so1, B + (size_t)bn1*Kd + _k0 + p1q*8, 16); \
        cp_commit(); \
    } while(0)

    LOAD_STAGE(0, 0);
    if(nch>1) LOAD_STAGE(1, 1); else cp_commit();
    if(nch>2) LOAD_STAGE(2, 2); else cp_commit();

    for(int ch=0; ch<nch; ch++){
        const int st = ch & 3;
        if(ch+1 < nch) cp_wait2(); else cp_wait0();
        __syncthreads();
        const uint32_t sb = sbase + st*STG_BYTES;
        #pragma unroll
        for(int ks=0; ks<2; ks++){
            const uint32_t kbyte = ks*32;
            uint32_t b2[2][4];
            ldsm4(b2[0], sb + boff0 + kbyte);
            ldsm4(b2[1], sb + boff0 + (uint32_t)(16*ASTR*2) + kbyte);
            #pragma unroll
            for(int mt=0; mt<4; mt++){
                uint32_t ah[4];
                ldsm4(ah, sb + aoff0 + (uint32_t)(mt*16*ASTR*2) + kbyte);
                #pragma unroll
                for(int nt=0; nt<4; nt++){
                    const int n2 = nt>>1, od = nt&1;
                    uint32_t bb[2] = { b2[n2][od], b2[n2][od+2] };
                    mma_f16(acc[mt][nt], ah, bb);
                }
            }
        }
        if(ch+NSTG-1 < nch) LOAD_STAGE(ch+NSTG-1, (ch+NSTG-1)&3); else cp_commit();
    }

    // epilogue (direct per-thread stores)
    #pragma unroll
    for(int mt=0; mt<4; mt++){
        #pragma unroll
        for(int nt=0; nt<4; nt++){
            int c = bx*128 + wn*32 + nt*8 + tg*2;
            float bb0, bb1;
            if(EPI==3){
                const float* bp = (c<256) ? bias : ((c<512) ? bias2 : bias3);
                int cc = c & 255;
                bb0 = bp[cc]; bb1 = bp[cc+1];
            } else {
                bb0 = bias[c]; bb1 = bias[c+1];
            }
            #pragma unroll
            for(int hf=0; hf<2; hf++){
                int r = by*128 + wm*64 + mt*16 + g + hf*8;
                if(r >= Mr) continue;
                float v0 = acc[mt][nt][hf*2+0] + bb0;
                float v1 = acc[mt][nt][hf*2+1] + bb1;
                if(EPI==3){
                    int plane = c>>8, cc = c&255;
                    *(uint32_t*)(Ch + (size_t)plane*BNc*Dc + (size_t)r*Dc + cc) = pkh2(v0, v1);
                    continue;
                }
                size_t off = (size_t)r*Nco + c;
                if(EPI==1){
                    float2 rv = *(const float2*)(R + off);
                    v0 += rv.x; v1 += rv.y;
                    *(float2*)(C + off) = make_float2(v0, v1);
                }
                if(EPI==2){
                    v0 = gelu_exact(v0); v1 = gelu_exact(v1);
                    *(uint32_t*)(Ch + off) = pkh2(v0, v1);
                }
            }
        }
    }
}

// ---------------- FAVOR+ K stabilizer: global max of dd (no stores) ----------------
__global__ __launch_bounds__(256) void kmax_kernel(const __half* __restrict__ K, const float* __restrict__ proj, int l){
    int bh = blockIdx.y; int b = bh>>3, h = bh&7;
    int n0 = blockIdx.x*32;
    __shared__ float sprojT[32][112];
    __shared__ float sxn[32][32];
    __shared__ float sred[256];
    int tid = threadIdx.x;
    for(int idx=tid; idx<Mc*DHc; idx+=256){ int m=idx>>5, d=idx&31; sprojT[d][m]=proj[idx]; }
    {
        int r = tid>>3, q4 = tid&7; int n = n0+r;
        const __half* kp = K + (size_t)(b*Nc+n)*Dc + h*DHc + q4*4;
        if(n<Nc){
            __half2 p0 = *(const __half2*)kp;
            __half2 p1 = *(const __half2*)(kp+2);
            sxn[r][q4*4+0]=__half2float(p0.x)*XN_SCALE; sxn[r][q4*4+1]=__half2float(p0.y)*XN_SCALE;
            sxn[r][q4*4+2]=__half2float(p1.x)*XN_SCALE; sxn[r][q4*4+3]=__half2float(p1.y)*XN_SCALE;
        } else {
            sxn[r][q4*4+0]=0.f; sxn[r][q4*4+1]=0.f; sxn[r][q4*4+2]=0.f; sxn[r][q4*4+3]=0.f;
        }
    }
    __syncthreads();
    float lmax = -3.4e38f;
    for(int idx=tid; idx<32*Mc; idx+=256){
        int r=idx/Mc, m=idx%Mc; int n=n0+r;
        float acc=0.f;
        #pragma unroll
        for(int d=0;d<32;d++) acc += sxn[r][d]*sprojT[d][m];
        if(n<Nc) lmax=fmaxf(lmax,acc);
    }
    sred[tid]=lmax; __syncthreads();
    for(int st=128;st;st>>=1){ if(tid<st) sred[tid]=fmaxf(sred[tid],sred[tid+st]); __syncthreads(); }
    if(tid==0) atomicMax(&g_ustab[l], fflip(sred[0]));
}

// ---------------- fused kf recompute + exp -> ctx/ksum (chunked, deterministic) ----------------
__global__ __launch_bounds__(256) void ctx_partial_kernel(const __half* __restrict__ K, const __half* __restrict__ V,
                                                          const float* __restrict__ proj, int l){
    int ch=blockIdx.x, bh=blockIdx.y; int b=bh>>3, h=bh&7;
    int nstart=ch*CR;
    int nend = nstart+CR < Nc ? nstart+CR : Nc;
    float stab = funflip(g_ustab[l]);
    __shared__ float sprojT[32][112];
    __shared__ float sxn[4][32];
    __shared__ float skf[4][112];
    __shared__ float sv[4][32];
    int tid=threadIdx.x;
    int txd=tid&7, ty=tid>>3;
    for(int idx=tid; idx<Mc*DHc; idx+=256){ int m=idx>>5, d=idx&31; sprojT[d][m]=proj[idx]; }
    float acc[4][4]; float ks[4];
    #pragma unroll
    for(int k=0;k<4;k++){ ks[k]=0.f;
        #pragma unroll
        for(int j=0;j<4;j++) acc[k][j]=0.f; }
    for(int n=nstart;n<nend;n+=4){
        __syncthreads();
        if(tid<128){
            int nn=tid>>5, d=tid&31; int gn=n+nn;
            if(gn<nend){
                sxn[nn][d] = __half2float(K[((size_t)(b*Nc+gn))*Dc + h*DHc + d])*XN_SCALE;
                sv[nn][d]  = __half2float(V[((size_t)(b*Nc+gn))*Dc + h*DHc + d]);
            } else {
                sxn[nn][d] = 0.f; sv[nn][d] = 0.f;
            }
        }
        __syncthreads();
        for(int idx=tid;idx<4*Mc;idx+=256){
            int nn=idx/Mc, m=idx%Mc; int gn=n+nn;
            float kv = 0.f;
            if(gn<nend){
                float dd=0.f, dg=0.f;
                #pragma unroll
                for(int d=0;d<32;d++){ float xv=sxn[nn][d]; dd += xv*sprojT[d][m]; dg += xv*xv; }
                kv = M_RSQRT*(__expf(dd - 0.5f*dg - stab) + FEPS);
            }
            skf[nn][m] = kv;
        }
        __syncthreads();
        #pragma unroll
        for(int nn=0;nn<4;nn++){
            float4 vv = *(const float4*)&sv[nn][txd*4];
            #pragma unroll
            for(int k=0;k<4;k++){
                int m = ty + 32*k;
                if(m<Mc){
                    float kv = skf[nn][m];
                    acc[k][0]+=kv*vv.x; acc[k][1]+=kv*vv.y;
                    acc[k][2]+=kv*vv.z; acc[k][3]+=kv*vv.w;
                    if(txd==0) ks[k]+=kv;
                }
            }
        }
    }
    #pragma unroll
    for(int k=0;k<4;k++){
        int m = ty + 32*k;
        if(m<Mc){
            float* dst = g_ctxp + ((((size_t)ch*BHc+bh)*Mc+m)*DHc) + txd*4;
            dst[0]=acc[k][0]; dst[1]=acc[k][1]; dst[2]=acc[k][2]; dst[3]=acc[k][3];
            if(txd==0) g_ksump[((size_t)ch*BHc+bh)*Mc+m]=ks[k];
        }
    }
}

__global__ void ctx_reduce_kernel(){
    int bh = blockIdx.x;
    for(int idx=threadIdx.x; idx<Mc*DHc; idx+=256){
        float s=0.f;
        for(int ch=0;ch<CH;ch++) s += g_ctxp[((size_t)ch*BHc+bh)*Mc*DHc + idx];
        g_ctx[(size_t)bh*Mc*DHc + idx]=s;
    }
    for(int idx=threadIdx.x; idx<Mc; idx+=256){
        float s=0.f;
        for(int ch=0;ch<CH;ch++) s += g_ksump[((size_t)ch*BHc+bh)*Mc + idx];
        g_ksum[bh*Mc+idx]=s;
    }
}

// ---------------- fused: qf features + o = (qf @ ctx) / (qf . ksum) -> fp16 ----------------
#define AT_PROJ 0
#define AT_XN   3584
#define AT_QF   5696
#define AT_CTX  12928
#define AT_KS   16448
#define AT_DEN  16560
#define ATT_SMEM ((16560+64)*4)

__global__ __launch_bounds__(128) void attn_out_fused(const __half* __restrict__ Q, const float* __restrict__ proj){
    extern __shared__ float sm[];
    float* sprojT = sm + AT_PROJ;   // [32][112]
    float* sxn    = sm + AT_XN;     // [64][33]
    float* sqf    = sm + AT_QF;     // [64][113]
    float* sctx   = sm + AT_CTX;    // [110*32]
    float* sks    = sm + AT_KS;     // [112]
    float* sden   = sm + AT_DEN;    // [64]
    int bh = blockIdx.y; int b = bh>>3, h = bh&7;
    int n0 = blockIdx.x*64;
    int tid = threadIdx.x;

    for(int idx=tid; idx<Mc*DHc; idx+=128){ int m=idx>>5, d=idx&31; sprojT[d*112+m]=proj[idx]; }
    if(tid<64){ int d=tid>>1, m=110+(tid&1); sprojT[d*112+m]=0.f; }
    for(int idx=tid; idx<64*32; idx+=128){
        int r=idx>>5, d=idx&31; int n=n0+r;
        sxn[r*33+d] = (n<Nc)? __half2float(Q[((size_t)(b*Nc+n))*Dc + h*DHc + d])*XN_SCALE : 0.f;
    }
    for(int idx=tid; idx<Mc*DHc; idx+=128) sctx[idx]=g_ctx[(size_t)bh*Mc*DHc+idx];
    for(int idx=tid; idx<Mc; idx+=128) sks[idx]=g_ksum[bh*Mc+idx];
    __syncthreads();

    {
        int rg = tid>>4, ml = tid&15;
        for(int rb=0; rb<64; rb+=8){
            int r = rb + rg;
            float a[7];
            #pragma unroll
            for(int j=0;j<7;j++) a[j]=0.f;
            #pragma unroll
            for(int d=0; d<32; d++){
                float xv = sxn[r*33+d];
                #pragma unroll
                for(int j=0;j<7;j++) a[j] += xv * sprojT[d*112 + ml + j*16];
            }
            #pragma unroll
            for(int j=0;j<7;j++){ int m = ml + j*16; if(m<Mc) sqf[r*113+m]=a[j]; }
        }
    }
    __syncthreads();

    int warp=tid>>5, lane=tid&31;
    for(int r=warp; r<64; r+=4){
        float mx=-3.4e38f;
        for(int m=lane;m<Mc;m+=32) mx=fmaxf(mx, sqf[r*113+m]);
        #pragma unroll
        for(int o=16;o;o>>=1) mx=fmaxf(mx,__shfl_xor_sync(0xffffffffu,mx,o));
        float xv=sxn[r*33+lane]; float dg=xv*xv;
        #pragma unroll
        for(int o=16;o;o>>=1) dg+=__shfl_xor_sync(0xffffffffu,dg,o);
        float sub = 0.5f*dg + mx;
        for(int m=lane;m<Mc;m+=32)
            sqf[r*113+m] = M_RSQRT*(__expf(sqf[r*113+m]-sub) + FEPS);
    }
    __syncthreads();

    for(int r=warp; r<64; r+=4){
        float dp=0.f;
        for(int m=lane;m<Mc;m+=32) dp += sqf[r*113+m]*sks[m];
        #pragma unroll
        for(int o=16;o;o>>=1) dp += __shfl_xor_sync(0xffffffffu,dp,o);
        if(lane==0) sden[r]=dp;
    }
    __syncthreads();

    int tx = tid&7, ty = tid>>3;
    float acc[4][4];
    #pragma unroll
    for(int i=0;i<4;i++)
        #pragma unroll
        for(int j=0;j<4;j++) acc[i][j]=0.f;
    for(int m=0;m<Mc;m++){
        float4 cv = *(const float4*)&sctx[m*DHc + tx*4];
        #pragma unroll
        for(int i=0;i<4;i++){
            float qv = sqf[(ty*4+i)*113+m];
            acc[i][0]+=qv*cv.x; acc[i][1]+=qv*cv.y; acc[i][2]+=qv*cv.z; acc[i][3]+=qv*cv.w;
        }
    }
    #pragma unroll
    for(int i=0;i<4;i++){
        int r = ty*4+i; int n = n0+r;
        if(n<Nc){
            float inv = 1.f/sden[r];
            float v0=acc[i][0]*inv, v1=acc[i][1]*inv, v2=acc[i][2]*inv, v3=acc[i][3]*inv;
            size_t off = ((size_t)(b*Nc+n))*Dc + h*DHc + tx*4;
            uint2 ph; ph.x = pkh2(v0,v1); ph.y = pkh2(v2,v3);
            *(uint2*)(g_oh + off) = ph;
        }
    }
}

// ---------------- final projection ----------------
__global__ void final_kernel(const float* __restrict__ pw, const float* __restrict__ pb, float* __restrict__ out){
    int j = threadIdx.x;
    float a0=0,a1=0,a2=0,a3=0;
    for(int d=0;d<Dc;d++){
        float w = pw[d*Dc+j];
        a0 += g_x[(size_t)(0*Nc)*Dc + d]*w;
        a1 += g_x[(size_t)(1*Nc)*Dc + d]*w;
        a2 += g_x[(size_t)(2*Nc)*Dc + d]*w;
        a3 += g_x[(size_t)(3*Nc)*Dc + d]*w;
    }
    float bj = pb[j];
    out[0*Dc+j]=a0+bj; out[1*Dc+j]=a1+bj; out[2*Dc+j]=a2+bj; out[3*Dc+j]=a3+bj;
}

// ---------------- launch ----------------
extern "C" void kernel_launch(void* const* d_in, const int* in_sizes, int n_in,
                              void* d_out, int out_size){
    const float* expr      = (const float*)d_in[0];
    const float* token_emb = (const float*)d_in[1];
    const float* cls_token = (const float*)d_in[2];
    const float* ln1_g     = (const float*)d_in[3];
    const float* ln1_b     = (const float*)d_in[4];
    const float* wq        = (const float*)d_in[5];
    const float* bq        = (const float*)d_in[6];
    const float* wk        = (const float*)d_in[7];
    const float* bk        = (const float*)d_in[8];
    const float* wv        = (const float*)d_in[9];
    const float* bv        = (const float*)d_in[10];
    const float* wo        = (const float*)d_in[11];
    const float* bo        = (const float*)d_in[12];
    const float* ln2_g     = (const float*)d_in[13];
    const float* ln2_b     = (const float*)d_in[14];
    const float* w1        = (const float*)d_in[15];
    const float* b1        = (const float*)d_in[16];
    const float* w2        = (const float*)d_in[17];
    const float* b2        = (const float*)d_in[18];
    const float* proj_w    = (const float*)d_in[19];
    const float* proj_b    = (const float*)d_in[20];
    const float* projs     = (const float*)d_in[21];
    float* out = (float*)d_out;

    float *px;
    __half *pqkvh, *phh, *poh, *pffh, *pw;
    cudaGetSymbolAddress((void**)&px,    g_x);
    cudaGetSymbolAddress((void**)&pqkvh, g_qkvh);
    cudaGetSymbolAddress((void**)&phh,   g_hh);
    cudaGetSymbolAddress((void**)&poh,   g_oh);
    cudaGetSymbolAddress((void**)&pffh,  g_ffh);
    cudaGetSymbolAddress((void**)&pw,    g_wt);
    __half* pq = pqkvh;
    __half* pk = pqkvh + (size_t)BNc*Dc;
    __half* pv = pqkvh + (size_t)2*BNc*Dc;

    cudaFuncSetAttribute(hmma_gemm<1>, cudaFuncAttributeMaxDynamicSharedMemorySize, GEMM_SMEM);
    cudaFuncSetAttribute(hmma_gemm<2>, cudaFuncAttributeMaxDynamicSharedMemorySize, GEMM_SMEM);
    cudaFuncSetAttribute(hmma_gemm<3>, cudaFuncAttributeMaxDynamicSharedMemorySize, GEMM_SMEM);
    cudaFuncSetAttribute(attn_out_fused, cudaFuncAttributeMaxDynamicSharedMemorySize, ATT_SMEM);

    init_kernel<<<1,1>>>();
    rowsum_kernel<<<Bc,256>>>(expr);
    emax_kernel<<<(Bc*Gc+255)/256,256>>>(expr);
    embed_kernel<<<BNc,256>>>(token_emb, cls_token);

    // weight conversion: transpose -> fp16 (QKV rows 0-767 fused layout)
    for(int l=0;l<Lc;l++){
        size_t wb = (size_t)l*WSTRIDE;
        wconv_kernel<<<(Dc*Dc+255)/256,256>>>(wq + (size_t)l*Dc*Dc, pw+wb,        Dc, Dc);
        wconv_kernel<<<(Dc*Dc+255)/256,256>>>(wk + (size_t)l*Dc*Dc, pw+wb+65536,  Dc, Dc);
        wconv_kernel<<<(Dc*Dc+255)/256,256>>>(wv + (size_t)l*Dc*Dc, pw+wb+131072, Dc, Dc);
        wconv_kernel<<<(Dc*Dc+255)/256,256>>>(wo + (size_t)l*Dc*Dc, pw+wb+196608, Dc, Dc);
        wconv_kernel<<<(Dc*FFc+255)/256,256>>>(w1 + (size_t)l*Dc*FFc, pw+wb+262144, Dc, FFc);
        wconv_kernel<<<(Dc*FFc+255)/256,256>>>(w2 + (size_t)l*FFc*Dc, pw+wb+524288, FFc, Dc);
    }

    const int GY = (BNc+127)/128;          // 529
    dim3 gQKV(6, GY);                      // N=768
    dim3 gD(Dc/128, GY);                   // (2, 529)
    dim3 gFF(FFc/128, GY);                 // (8, 529)
    dim3 gfeat((Nc+31)/32, BHc);
    dim3 gctx(CH, BHc);
    dim3 gattn((Nc+63)/64, BHc);
    int lnb = (BNc+7)/8;

    for(int l=0;l<Lc;l++){
        size_t wb = (size_t)l*WSTRIDE;
        const __half *wqkv=pw+wb;
        const __half *wo_t=pw+wb+196608;
        const __half *w1_t=pw+wb+262144;
        const __half *w2_t=pw+wb+524288;
        const float* pr_l = projs + (size_t)l*Mc*DHc;

        ln_kernel<<<lnb,256>>>(px, ln1_g + l*Dc, ln1_b + l*Dc, phh);
        hmma_gemm<3><<<gQKV,256,GEMM_SMEM>>>(phh, wqkv,
                                             bq + l*Dc, bk + l*Dc, bv + l*Dc,
                                             nullptr, nullptr, pqkvh, BNc, Dc, 768);
        kmax_kernel<<<gfeat,256>>>(pk, pr_l, l);
        ctx_partial_kernel<<<gctx,256>>>(pk, pv, pr_l, l);
        ctx_reduce_kernel<<<BHc,256>>>();
        attn_out_fused<<<gattn,128,ATT_SMEM>>>(pq, pr_l);
        hmma_gemm<1><<<gD,256,GEMM_SMEM>>>(poh, wo_t,
                                           bo + l*Dc, nullptr, nullptr,
                                           px, px, nullptr, BNc, Dc, Dc);
        ln_kernel<<<lnb,256>>>(px, ln2_g + l*Dc, ln2_b + l*Dc, phh);
        hmma_gemm<2><<<gFF,256,GEMM_SMEM>>>(phh, w1_t,
                                            b1 + l*FFc, nullptr, nullptr,
                                            nullptr, nullptr, pffh, BNc, Dc, FFc);
        hmma_gemm<1><<<gD,256,GEMM_SMEM>>>(pffh, w2_t,
                                           b2 + l*Dc, nullptr, nullptr,
                                           px, px, nullptr, BNc, FFc, Dc);
    }
    final_kernel<<<1,256>>>(proj_w, proj_b, out);
}

// round 14
// speedup vs baseline: 22.4914x; 22.4297x over previous
#include <cuda_runtime.h>
#include <math.h>
#include <stdint.h>

#define Bc   4
#define Gc   16906
#define Nc   16907
#define Dc   256
#define Hc   8
#define DHc  32
#define Mc   110
#define Lc   6
#define FFc  1024
#define Sc   8                 // distinct states per batch: bins 0..6 + cls(7)
#define Rc   (Bc*Sc)           // 32 state rows

#define XN_SCALE   0.42044820762685725f   // 32^-0.25
#define M_RSQRT    0.09534625892455922f   // 110^-0.5
#define FEPS       1e-4f

// ---------------- device scratch (tiny) ----------------
__device__ __align__(128) float g_e[Bc*Gc];
__device__ float    g_rowsum[Bc];
__device__ unsigned g_umax;
__device__ unsigned g_ustab[Lc];
__device__ int      g_cnt[Rc];
__device__ __align__(128) float g_sx[Rc*Dc];
__device__ __align__(128) float g_sh[Rc*Dc];
__device__ __align__(128) float g_sq[Rc*Dc];
__device__ __align__(128) float g_sk[Rc*Dc];
__device__ __align__(128) float g_sv[Rc*Dc];
__device__ __align__(128) float g_so[Rc*Dc];
__device__ __align__(128) float g_sff[Rc*FFc];

__device__ __forceinline__ unsigned fflip(float f){
    unsigned u = __float_as_uint(f);
    return (u & 0x80000000u) ? ~u : (u | 0x80000000u);
}
__device__ __forceinline__ float funflip(unsigned u){
    unsigned b = (u & 0x80000000u) ? (u ^ 0x80000000u) : ~u;
    return __uint_as_float(b);
}
__device__ __forceinline__ float gelu_exact(float x){
    return 0.5f*x*(1.0f + erff(x*0.7071067811865476f));
}

// ---------------- preprocessing ----------------
__global__ void init_kernel(){
    g_umax = 0u;
    for(int l=0;l<Lc;l++) g_ustab[l] = 0u;
    for(int i=0;i<Rc;i++) g_cnt[i] = ((i&7)==7) ? 1 : 0;   // cls count = 1
}

__global__ void rowsum_kernel(const float* __restrict__ expr){
    __shared__ float sred[256];
    int b = blockIdx.x;
    float s = 0.f;
    for(int i=threadIdx.x;i<Gc;i+=256) s += fabsf(expr[(size_t)b*Gc+i]);
    sred[threadIdx.x]=s; __syncthreads();
    for(int st=128;st;st>>=1){ if(threadIdx.x<st) sred[threadIdx.x]+=sred[threadIdx.x+st]; __syncthreads(); }
    if(threadIdx.x==0) g_rowsum[b]=s=sred[0];
}

__global__ void emax_kernel(const float* __restrict__ expr){
    __shared__ float sred[256];
    int i = blockIdx.x*256 + threadIdx.x;
    float e = 0.f;
    if(i < Bc*Gc){
        int b = i / Gc;
        float denom = fmaxf(g_rowsum[b], 1e-12f);
        e = log1pf(expr[i]/denom*1e4f);
        g_e[i] = e;
    }
    sred[threadIdx.x]=e; __syncthreads();
    for(int st=128;st;st>>=1){ if(threadIdx.x<st) sred[threadIdx.x]=fmaxf(sred[threadIdx.x],sred[threadIdx.x+st]); __syncthreads(); }
    if(threadIdx.x==0) atomicMax(&g_umax, fflip(sred[0]));
}

// histogram of bin indices (identical binning to validated embed path)
__global__ void hist_kernel(){
    int i = blockIdx.x*256 + threadIdx.x;
    if(i >= Bc*Gc) return;
    int b = i / Gc;
    float e = g_e[i];
    float maxe = funflip(g_umax);
    float step = maxe/7.0f;
    int t = (0.0f < e) ? 1 : 0;
    #pragma unroll
    for(int j=1;j<7;j++) t += ((float)j*step < e) ? 1 : 0;
    if(t>6) t=6;
    atomicAdd(&g_cnt[b*8+t], 1);
}

// build initial 32 state rows
__global__ void seed_kernel(const float* __restrict__ temb, const float* __restrict__ cls){
    int r = blockIdx.x;         // 0..31
    int d = threadIdx.x;        // 0..255
    int s = r & 7;
    float v = (s==7) ? cls[d] : temb[s*Dc + d];
    g_sx[(size_t)r*Dc + d] = v;
}

// ---------------- layernorm over 32 rows (8 rows/block) ----------------
__global__ void ln32_kernel(const float* __restrict__ X, const float* __restrict__ g,
                            const float* __restrict__ bb, float* __restrict__ Y){
    int warp=threadIdx.x>>5, lane=threadIdx.x&31;
    int row = blockIdx.x*8 + warp;
    if(row>=Rc) return;
    const float4* xr=(const float4*)(X+(size_t)row*Dc);
    float4 v0=xr[lane], v1=xr[lane+32];
    float s = v0.x+v0.y+v0.z+v0.w+v1.x+v1.y+v1.z+v1.w;
    #pragma unroll
    for(int o=16;o;o>>=1) s += __shfl_xor_sync(0xffffffffu,s,o);
    float mu = s*(1.f/256.f);
    float d0=v0.x-mu,d1=v0.y-mu,d2=v0.z-mu,d3=v0.w-mu;
    float d4=v1.x-mu,d5=v1.y-mu,d6=v1.z-mu,d7=v1.w-mu;
    float sq = d0*d0+d1*d1+d2*d2+d3*d3+d4*d4+d5*d5+d6*d6+d7*d7;
    #pragma unroll
    for(int o=16;o;o>>=1) sq += __shfl_xor_sync(0xffffffffu,sq,o);
    float rstd = rsqrtf(sq*(1.f/256.f) + 1e-5f);
    float4 g0=((const float4*)g)[lane],  g1=((const float4*)g)[lane+32];
    float4 b0=((const float4*)bb)[lane], b1=((const float4*)bb)[lane+32];
    float4 y0, y1;
    y0.x=d0*rstd*g0.x+b0.x; y0.y=d1*rstd*g0.y+b0.y; y0.z=d2*rstd*g0.z+b0.z; y0.w=d3*rstd*g0.w+b0.w;
    y1.x=d4*rstd*g1.x+b1.x; y1.y=d5*rstd*g1.y+b1.y; y1.z=d6*rstd*g1.z+b1.z; y1.w=d7*rstd*g1.w+b1.w;
    ((float4*)(Y+(size_t)row*Dc))[lane]    = y0;
    ((float4*)(Y+(size_t)row*Dc))[lane+32] = y1;
}

// ---------------- GEMV: Y[32][N] = act(X[32][K] @ W[K][N] + bias)  ----------------
// MODE: 0 plain ; 1 +residual ; 2 gelu
template<int MODE>
__global__ void gemv32(const float* __restrict__ X, const float* __restrict__ W,
                       const float* __restrict__ bias, const float* __restrict__ Rres,
                       float* __restrict__ Y, int K, int N)
{
    __shared__ float sx[1024];
    int r = blockIdx.x;
    int c = blockIdx.y*256 + threadIdx.x;
    for(int i=threadIdx.x;i<K;i+=256) sx[i]=X[(size_t)r*K+i];
    __syncthreads();
    float a=0.f;
    #pragma unroll 8
    for(int k=0;k<K;k++) a += sx[k]*W[(size_t)k*N+c];
    a += bias[c];
    if(MODE==1) a += Rres[(size_t)r*N+c];
    if(MODE==2) a = gelu_exact(a);
    Y[(size_t)r*N+c]=a;
}

// ---------------- key stabilizer: global max of dd over occupied states ----------------
__global__ void stab32(const float* __restrict__ proj, int l){
    int bh = blockIdx.x; int b = bh>>3, h = bh&7;
    __shared__ float sp[Mc*DHc];
    __shared__ float xk[Sc][DHc];
    __shared__ float sred[256];
    int tid = threadIdx.x;
    for(int i=tid;i<Mc*DHc;i+=256) sp[i]=proj[i];
    { int s=tid>>5, d=tid&31; xk[s][d]=g_sk[(size_t)(b*8+s)*Dc + h*DHc + d]*XN_SCALE; }
    __syncthreads();
    float mx = -3.4e38f;
    for(int i=tid;i<Sc*Mc;i+=256){
        int s=i/Mc, m=i%Mc;
        if(g_cnt[b*8+s] > 0){
            float dd=0.f;
            #pragma unroll
            for(int d=0;d<DHc;d++) dd += xk[s][d]*sp[m*DHc+d];
            mx = fmaxf(mx, dd);
        }
    }
    sred[tid]=mx; __syncthreads();
    for(int st=128;st;st>>=1){ if(tid<st) sred[tid]=fmaxf(sred[tid],sred[tid+st]); __syncthreads(); }
    if(tid==0) atomicMax(&g_ustab[l], fflip(sred[0]));
}

// ---------------- fused attention over 8 states per (b,h) ----------------
__global__ void attn32(const float* __restrict__ proj, int l){
    int bh = blockIdx.x; int b = bh>>3, h = bh&7;
    __shared__ float sp[Mc*DHc];       // proj [m][d]
    __shared__ float xk[Sc][DHc], xq[Sc][DHc], xv[Sc][DHc];
    __shared__ float kf[Sc][112], qf[Sc][112];
    __shared__ float sctx[Mc*DHc];
    __shared__ float sksum[112];
    __shared__ float sden[Sc], dgk[Sc], dgq[Sc];
    __shared__ float scnt[Sc];
    int tid = threadIdx.x;
    int warp = tid>>5, lane = tid&31;

    for(int i=tid;i<Mc*DHc;i+=256) sp[i]=proj[i];
    { int s=tid>>5, d=tid&31;
      size_t off = (size_t)(b*8+s)*Dc + h*DHc + d;
      xk[s][d]=g_sk[off]*XN_SCALE;
      xq[s][d]=g_sq[off]*XN_SCALE;
      xv[s][d]=g_sv[off]; }
    if(tid<Sc) scnt[tid] = (float)g_cnt[b*8+tid];
    __syncthreads();

    // per-state 0.5*|x|^2 (8 warps, one state each)
    {
        float kk = xk[warp][lane]*xk[warp][lane];
        float qq = xq[warp][lane]*xq[warp][lane];
        #pragma unroll
        for(int o=16;o;o>>=1){ kk += __shfl_xor_sync(0xffffffffu,kk,o); qq += __shfl_xor_sync(0xffffffffu,qq,o); }
        if(lane==0){ dgk[warp]=0.5f*kk; dgq[warp]=0.5f*qq; }
    }
    __syncthreads();

    float stab = funflip(g_ustab[l]);
    // kf (key features with global stabilizer) and raw q dot-products
    for(int i=tid;i<Sc*Mc;i+=256){
        int s=i/Mc, m=i%Mc;
        float ddk=0.f, ddq=0.f;
        #pragma unroll
        for(int d=0;d<DHc;d++){ ddk += xk[s][d]*sp[m*DHc+d]; ddq += xq[s][d]*sp[m*DHc+d]; }
        kf[s][m] = M_RSQRT*(expf(ddk - dgk[s] - stab) + FEPS);
        qf[s][m] = ddq;
    }
    __syncthreads();

    // per-row q stabilizer + exp (8 warps)
    {
        float mx=-3.4e38f;
        for(int m=lane;m<Mc;m+=32) mx=fmaxf(mx, qf[warp][m]);
        #pragma unroll
        for(int o=16;o;o>>=1) mx=fmaxf(mx,__shfl_xor_sync(0xffffffffu,mx,o));
        for(int m=lane;m<Mc;m+=32)
            qf[warp][m] = M_RSQRT*(expf(qf[warp][m]-dgq[warp]-mx) + FEPS);
    }
    __syncthreads();

    // ctx[m][d] = sum_s cnt_s kf[s][m] v[s][d] ; ksum[m] = sum_s cnt_s kf[s][m]
    for(int i=tid;i<Mc*DHc;i+=256){
        int m=i>>5, d=i&31;
        float a=0.f;
        #pragma unroll
        for(int s=0;s<Sc;s++) a += scnt[s]*kf[s][m]*xv[s][d];
        sctx[i]=a;
    }
    for(int m=tid;m<Mc;m+=256){
        float a=0.f;
        #pragma unroll
        for(int s=0;s<Sc;s++) a += scnt[s]*kf[s][m];
        sksum[m]=a;
    }
    __syncthreads();

    // denominators (8 warps)
    {
        float a=0.f;
        for(int m=lane;m<Mc;m+=32) a += qf[warp][m]*sksum[m];
        #pragma unroll
        for(int o=16;o;o>>=1) a += __shfl_xor_sync(0xffffffffu,a,o);
        if(lane==0) sden[warp]=a;
    }
    __syncthreads();

    // o[s][d] = (qf[s] . ctx[:,d]) / den[s]
    {
        int s=tid>>5, d=tid&31;
        float a=0.f;
        for(int m=0;m<Mc;m++) a += qf[s][m]*sctx[m*DHc+d];
        g_so[(size_t)(b*8+s)*Dc + h*DHc + d] = a/sden[s];
    }
}

// ---------------- final projection (cls states) ----------------
__global__ void final32(const float* __restrict__ pw, const float* __restrict__ pb, float* __restrict__ out){
    int b = blockIdx.x, j = threadIdx.x;
    __shared__ float sx[Dc];
    sx[j] = g_sx[(size_t)(b*8+7)*Dc + j];
    __syncthreads();
    float a=0.f;
    #pragma unroll 8
    for(int d=0;d<Dc;d++) a += sx[d]*pw[(size_t)d*Dc+j];
    out[b*Dc+j] = a + pb[j];
}

// ---------------- launch ----------------
extern "C" void kernel_launch(void* const* d_in, const int* in_sizes, int n_in,
                              void* d_out, int out_size){
    const float* expr      = (const float*)d_in[0];
    const float* token_emb = (const float*)d_in[1];
    const float* cls_token = (const float*)d_in[2];
    const float* ln1_g     = (const float*)d_in[3];
    const float* ln1_b     = (const float*)d_in[4];
    const float* wq        = (const float*)d_in[5];
    const float* bq        = (const float*)d_in[6];
    const float* wk        = (const float*)d_in[7];
    const float* bk        = (const float*)d_in[8];
    const float* wv        = (const float*)d_in[9];
    const float* bv        = (const float*)d_in[10];
    const float* wo        = (const float*)d_in[11];
    const float* bo        = (const float*)d_in[12];
    const float* ln2_g     = (const float*)d_in[13];
    const float* ln2_b     = (const float*)d_in[14];
    const float* w1        = (const float*)d_in[15];
    const float* b1        = (const float*)d_in[16];
    const float* w2        = (const float*)d_in[17];
    const float* b2        = (const float*)d_in[18];
    const float* proj_w    = (const float*)d_in[19];
    const float* proj_b    = (const float*)d_in[20];
    const float* projs     = (const float*)d_in[21];
    float* out = (float*)d_out;

    float *psx, *psh, *psq, *psk, *psv, *pso, *psff;
    cudaGetSymbolAddress((void**)&psx,  g_sx);
    cudaGetSymbolAddress((void**)&psh,  g_sh);
    cudaGetSymbolAddress((void**)&psq,  g_sq);
    cudaGetSymbolAddress((void**)&psk,  g_sk);
    cudaGetSymbolAddress((void**)&psv,  g_sv);
    cudaGetSymbolAddress((void**)&pso,  g_so);
    cudaGetSymbolAddress((void**)&psff, g_sff);

    init_kernel<<<1,1>>>();
    rowsum_kernel<<<Bc,256>>>(expr);
    emax_kernel<<<(Bc*Gc+255)/256,256>>>(expr);
    hist_kernel<<<(Bc*Gc+255)/256,256>>>();
    seed_kernel<<<Rc,256>>>(token_emb, cls_token);

    dim3 gD(Rc,1);
    dim3 gFF(Rc,FFc/256);
    for(int l=0;l<Lc;l++){
        const float* wq_l = wq + (size_t)l*Dc*Dc;  const float* bq_l = bq + l*Dc;
        const float* wk_l = wk + (size_t)l*Dc*Dc;  const float* bk_l = bk + l*Dc;
        const float* wv_l = wv + (size_t)l*Dc*Dc;  const float* bv_l = bv + l*Dc;
        const float* wo_l = wo + (size_t)l*Dc*Dc;  const float* bo_l = bo + l*Dc;
        const float* w1_l = w1 + (size_t)l*Dc*FFc; const float* b1_l = b1 + l*FFc;
        const float* w2_l = w2 + (size_t)l*FFc*Dc; const float* b2_l = b2 + l*Dc;
        const float* pr_l = projs + (size_t)l*Mc*DHc;

        ln32_kernel<<<4,256>>>(psx, ln1_g + l*Dc, ln1_b + l*Dc, psh);
        gemv32<0><<<gD,256>>>(psh, wq_l, bq_l, nullptr, psq, Dc, Dc);
        gemv32<0><<<gD,256>>>(psh, wk_l, bk_l, nullptr, psk, Dc, Dc);
        gemv32<0><<<gD,256>>>(psh, wv_l, bv_l, nullptr, psv, Dc, Dc);
        stab32<<<Rc,256>>>(pr_l, l);
        attn32<<<Rc,256>>>(pr_l, l);
        gemv32<1><<<gD,256>>>(pso, wo_l, bo_l, psx, psx, Dc, Dc);
        ln32_kernel<<<4,256>>>(psx, ln2_g + l*Dc, ln2_b + l*Dc, psh);
        gemv32<2><<<gFF,256>>>(psh, w1_l, b1_l, nullptr, psff, Dc, FFc);
        gemv32<1><<<gD,256>>>(psff, w2_l, b2_l, psx, psx, FFc, Dc);
    }
    final32<<<Bc,256>>>(proj_w, proj_b, out);
}